// round 1
// baseline (speedup 1.0000x reference)
#include <cuda_runtime.h>
#include <cuda_bf16.h>

// Problem geometry
#define BATCH     8
#define HIN       1024
#define WIN       1024
#define HC        1025
#define WC        1025
#define CELLS     (HC * WC)          // 1,050,625 cells per batch
#define CELLS_PAD 1050688            // padded per-batch code stride (mult of 64)
#define K_PER_T   64                 // cells per thread
#define TPB       256
#define CPB       (TPB * K_PER_T)    // 16384 cells per block
#define NBB       65                 // blocks per batch: ceil(CELLS/CPB)
#define NBLK      (BATCH * NBB)      // 520 blocks total
#define NROWS     (2 * BATCH * CELLS)  // 16,810,000 output rows (4 floats each)

// -------- scratch (static device globals; no allocation allowed) ----------
__device__ unsigned char g_codes[(size_t)BATCH * CELLS_PAD];
__device__ unsigned int  g_cnt1[NBLK];
__device__ unsigned int  g_cnt2[NBLK];
__device__ unsigned int  g_off1[NBLK];
__device__ unsigned int  g_off2[NBLK];
__device__ unsigned int  g_total;

// Midpoint offsets per code, derived from FIRST table + CORNERS:
// row = [y + f.x, x + f.y, y + f.z, x + f.w]
__constant__ float4 c_F[16] = {
    { 0.0f,  0.0f,  0.0f,  0.0f},  // 0  (invalid)
    { 0.0f, -0.5f,  0.5f,  0.0f},  // 1
    { 0.5f,  0.0f,  0.0f,  0.5f},  // 2
    { 0.0f, -0.5f,  0.0f,  0.5f},  // 3
    { 0.0f,  0.5f, -0.5f,  0.0f},  // 4
    { 0.0f, -0.5f,  0.5f,  0.0f},  // 5
    { 0.5f,  0.0f, -0.5f,  0.0f},  // 6
    { 0.0f, -0.5f, -0.5f,  0.0f},  // 7
    {-0.5f,  0.0f,  0.0f, -0.5f},  // 8
    {-0.5f,  0.0f,  0.5f,  0.0f},  // 9
    { 0.5f,  0.0f,  0.0f,  0.5f},  // 10
    {-0.5f,  0.0f,  0.0f,  0.5f},  // 11
    { 0.0f,  0.5f,  0.0f, -0.5f},  // 12
    { 0.0f,  0.5f,  0.5f,  0.0f},  // 13
    { 0.5f,  0.0f,  0.0f, -0.5f},  // 14
    { 0.0f,  0.0f,  0.0f,  0.0f},  // 15 (invalid)
};
// SECOND[5]  = (0, 0.5, -0.5, 0), SECOND[10] = (-0.5, 0, 0, -0.5) inlined below.

// ---------------- Pass 1: compute codes, per-block counts ------------------
__global__ __launch_bounds__(TPB)
void ms_pass1(const float* __restrict__ in)
{
    const int bk  = blockIdx.x;
    const int b   = bk / NBB;
    const int blk = bk - b * NBB;
    const float* __restrict__ img = in + (size_t)b * HIN * WIN;
    unsigned char* __restrict__ codes = g_codes + (size_t)b * CELLS_PAD;

    unsigned int base = (unsigned)blk * CPB + (unsigned)threadIdx.x * K_PER_T;
    unsigned int c1 = 0, c2 = 0;

    if (base < CELLS) {
        unsigned int idx = base;
        int y = (int)(idx / WC);
        int x = (int)(idx - (unsigned)y * WC);
        int yA = max(y - 1, 0);
        int yB = min(y, HIN - 1);
        const float* rA = img + (size_t)yA * WIN;
        const float* rB = img + (size_t)yB * WIN;
        int xL = max(x - 1, 0);
        float nwv = rA[xL];
        float swv = rB[xL];

        #pragma unroll 4
        for (int k = 0; k < K_PER_T; k++) {
            if (idx >= CELLS) break;
            int xR = min(x, WIN - 1);
            float nev = rA[xR];
            float sev = rB[xR];
            int code = (swv > 0.0f ? 1 : 0) | (sev > 0.0f ? 2 : 0) |
                       (nev > 0.0f ? 4 : 0) | (nwv > 0.0f ? 8 : 0);
            codes[idx] = (unsigned char)code;
            c1 += (unsigned)(code - 1) < 14u;   // 1..14
            c2 += (code == 5) | (code == 10);
            idx++; x++;
            if (x == WC) {
                x = 0; y++;
                yA = min(max(y - 1, 0), HIN - 1);
                yB = min(y, HIN - 1);
                rA = img + (size_t)yA * WIN;
                rB = img + (size_t)yB * WIN;
                nwv = rA[0];
                swv = rB[0];
            } else {
                nwv = nev;
                swv = sev;
            }
        }
    }

    // block reduction
    __shared__ unsigned int r1[8], r2[8];
    unsigned int lane = threadIdx.x & 31u, wid = threadIdx.x >> 5;
    unsigned int s1 = __reduce_add_sync(0xffffffffu, c1);
    unsigned int s2 = __reduce_add_sync(0xffffffffu, c2);
    if (lane == 0) { r1[wid] = s1; r2[wid] = s2; }
    __syncthreads();
    if (threadIdx.x == 0) {
        unsigned int t1 = 0, t2 = 0;
        #pragma unroll
        for (int i = 0; i < 8; i++) { t1 += r1[i]; t2 += r2[i]; }
        g_cnt1[bk] = t1;
        g_cnt2[bk] = t2;
    }
}

// ------------- Scan: block offsets, group bases, counts, total -------------
__global__ void ms_scan(float* __restrict__ out, int out_size)
{
    __shared__ unsigned int s1[NBLK], s2[NBLK];
    __shared__ unsigned int t1[BATCH], t2[BATCH];
    __shared__ unsigned int gb1[BATCH], gb2[BATCH];
    int tid = threadIdx.x;
    for (int i = tid; i < NBLK; i += blockDim.x) { s1[i] = g_cnt1[i]; s2[i] = g_cnt2[i]; }
    __syncthreads();

    if (tid < BATCH) {
        unsigned int s = 0;
        for (int i = 0; i < NBB; i++) s += s1[tid * NBB + i];
        t1[tid] = s;
    } else if (tid < 2 * BATCH) {
        int b = tid - BATCH;
        unsigned int s = 0;
        for (int i = 0; i < NBB; i++) s += s2[b * NBB + i];
        t2[b] = s;
    }
    __syncthreads();

    if (tid == 0) {
        unsigned int acc = 0;
        for (int b = 0; b < BATCH; b++) {
            gb1[b] = acc; acc += t1[b];
            gb2[b] = acc; acc += t2[b];
        }
        g_total = acc;
    }
    __syncthreads();

    // per-batch counts appended after the rows (as output dtype float32)
    if (tid < BATCH && out_size >= NROWS * 4 + BATCH)
        out[(size_t)NROWS * 4 + tid] = (float)(t1[tid] + t2[tid]);

    // exclusive scan of block counts within each (batch, table) group
    if (tid < BATCH) {
        unsigned int acc = gb1[tid];
        for (int i = 0; i < NBB; i++) {
            unsigned int v = s1[tid * NBB + i];
            g_off1[tid * NBB + i] = acc;
            acc += v;
        }
    } else if (tid < 2 * BATCH) {
        int b = tid - BATCH;
        unsigned int acc = gb2[b];
        for (int i = 0; i < NBB; i++) {
            unsigned int v = s2[b * NBB + i];
            g_off2[b * NBB + i] = acc;
            acc += v;
        }
    }
}

// ---------------- Pass 2: compact midpoint rows into output ----------------
__device__ __forceinline__ unsigned int block_exscan(unsigned int v)
{
    __shared__ unsigned int ws[8];
    unsigned int lane = threadIdx.x & 31u, wid = threadIdx.x >> 5;
    unsigned int inc = v;
    #pragma unroll
    for (int o = 1; o < 32; o <<= 1) {
        unsigned int u = __shfl_up_sync(0xffffffffu, inc, o);
        if (lane >= (unsigned)o) inc += u;
    }
    if (lane == 31) ws[wid] = inc;
    __syncthreads();
    if (threadIdx.x == 0) {
        unsigned int acc = 0;
        #pragma unroll
        for (int i = 0; i < 8; i++) { unsigned int t = ws[i]; ws[i] = acc; acc += t; }
    }
    __syncthreads();
    return inc - v + ws[wid];
}

__global__ __launch_bounds__(TPB)
void ms_pass2(float4* __restrict__ out4)
{
    const int bk  = blockIdx.x;
    const int b   = bk / NBB;
    const int blk = bk - b * NBB;
    const unsigned char* __restrict__ codes = g_codes + (size_t)b * CELLS_PAD;

    unsigned int base = (unsigned)blk * CPB + (unsigned)threadIdx.x * K_PER_T;
    unsigned int c1 = 0, c2 = 0;

    if (base < CELLS) {
        #pragma unroll 8
        for (int k = 0; k < K_PER_T; k++) {
            unsigned int idx = base + k;
            if (idx >= CELLS) break;
            unsigned int code = codes[idx];
            c1 += (code - 1u) < 14u;
            c2 += (code == 5u) | (code == 10u);
        }
    }

    unsigned int packed = c1 | (c2 << 16);
    unsigned int ex = block_exscan(packed);
    unsigned int p1 = g_off1[bk] + (ex & 0xFFFFu);
    unsigned int p2 = g_off2[bk] + (ex >> 16);

    if (base < CELLS) {
        unsigned int idx = base;
        int y = (int)(idx / WC);
        int x = (int)(idx - (unsigned)y * WC);
        float fy = (float)y, fx = (float)x;
        for (int k = 0; k < K_PER_T; k++) {
            if (idx >= CELLS) break;
            unsigned int code = codes[idx];
            if ((code - 1u) < 14u) {
                float4 f = c_F[code];
                out4[p1++] = make_float4(fy + f.x, fx + f.y, fy + f.z, fx + f.w);
            }
            if (code == 5u) {
                out4[p2++] = make_float4(fy, fx + 0.5f, fy - 0.5f, fx);
            } else if (code == 10u) {
                out4[p2++] = make_float4(fy - 0.5f, fx, fy, fx - 0.5f);
            }
            idx++; x++; fx += 1.0f;
            if (x == WC) { x = 0; fx = 0.0f; fy += 1.0f; }
        }
    }
}

// ---------------- Zero-fill tail [total, NROWS) ----------------------------
__global__ __launch_bounds__(256)
void ms_zero(float4* __restrict__ out4)
{
    unsigned int i = blockIdx.x * blockDim.x + threadIdx.x;
    unsigned int total = g_total;
    if (i < (unsigned)NROWS && i >= total)
        out4[i] = make_float4(0.0f, 0.0f, 0.0f, 0.0f);
}

// ---------------------------------------------------------------------------
extern "C" void kernel_launch(void* const* d_in, const int* in_sizes, int n_in,
                              void* d_out, int out_size)
{
    const float* coarse = (const float*)d_in[0];
    float* out = (float*)d_out;

    ms_pass1<<<NBLK, TPB>>>(coarse);
    ms_scan<<<1, 1024>>>(out, out_size);
    ms_pass2<<<NBLK, TPB>>>((float4*)out);
    ms_zero<<<(NROWS + 255) / 256, 256>>>((float4*)out);
}

// round 2
// speedup vs baseline: 2.3538x; 2.3538x over previous
#include <cuda_runtime.h>
#include <cuda_bf16.h>

// Problem geometry
#define BATCH   8
#define HIN     1024
#define WIN     1024
#define HC      1025               // code-grid rows
#define WC      1025               // code-grid cols
#define CELLS   (HC * WC)          // 1,050,625 cells per batch
#define WCP     1028               // padded code-row stride (mult of 4)
#define CSTRIDE (HC * WCP)         // per-batch code stride
#define RPB     8                  // cell-rows per block
#define NBB     129                // row-chunks per batch: ceil(1025/8)
#define NBLK    (BATCH * NBB)      // 1032 blocks
#define TPB     256
#define NROWS   (2 * BATCH * CELLS)  // 16,810,000 output rows (float4 each)

// -------- scratch (static device globals; no allocation allowed) ----------
__device__ unsigned char g_codes[(size_t)BATCH * CSTRIDE];
__device__ unsigned int  g_cnt1[NBLK];
__device__ unsigned int  g_cnt2[NBLK];
__device__ unsigned int  g_off1[NBLK];
__device__ unsigned int  g_off2[NBLK];
__device__ unsigned int  g_total;

// Midpoint offsets per code (FIRST table): row = [y+f.x, x+f.y, y+f.z, x+f.w]
__constant__ float4 c_F[16] = {
    { 0.0f,  0.0f,  0.0f,  0.0f},  // 0  (invalid)
    { 0.0f, -0.5f,  0.5f,  0.0f},  // 1
    { 0.5f,  0.0f,  0.0f,  0.5f},  // 2
    { 0.0f, -0.5f,  0.0f,  0.5f},  // 3
    { 0.0f,  0.5f, -0.5f,  0.0f},  // 4
    { 0.0f, -0.5f,  0.5f,  0.0f},  // 5
    { 0.5f,  0.0f, -0.5f,  0.0f},  // 6
    { 0.0f, -0.5f, -0.5f,  0.0f},  // 7
    {-0.5f,  0.0f,  0.0f, -0.5f},  // 8
    {-0.5f,  0.0f,  0.5f,  0.0f},  // 9
    { 0.5f,  0.0f,  0.0f,  0.5f},  // 10
    {-0.5f,  0.0f,  0.0f,  0.5f},  // 11
    { 0.0f,  0.5f,  0.0f, -0.5f},  // 12
    { 0.0f,  0.5f,  0.5f,  0.0f},  // 13
    { 0.5f,  0.0f,  0.0f, -0.5f},  // 14
    { 0.0f,  0.0f,  0.0f,  0.0f},  // 15 (invalid)
};
// SECOND[5] = (0, 0.5, -0.5, 0), SECOND[10] = (-0.5, 0, 0, -0.5) inlined.

// ---------------- Pass 1: codes + per-block counts (row-chunk blocks) ------
__global__ __launch_bounds__(TPB)
void ms_pass1(const float* __restrict__ in)
{
    const int bk    = blockIdx.x;
    const int b     = bk / NBB;
    const int chunk = bk - b * NBB;
    const int y0    = chunk * RPB;
    const int yend  = min(y0 + RPB, HC);
    const float* __restrict__ img = in + (size_t)b * HIN * WIN;
    unsigned char* __restrict__ crow0 = g_codes + (size_t)b * CSTRIDE;

    const int t    = threadIdx.x;
    const int col  = 4 * t;                  // 0..1020, float4 covers 4 cols
    const unsigned lane = t & 31u;

    // initial top row for y0: input row clamp(y0-1, 0, 1023)
    const float* rA = img + (size_t)max(min(y0 - 1, HIN - 1), 0) * WIN;
    float4 vA = *(const float4*)(rA + col);
    float lmA = __shfl_up_sync(0xffffffffu, vA.w, 1);
    if (lane == 0) lmA = (col > 0) ? rA[col - 1] : vA.x;

    unsigned c1 = 0, c2 = 0;

    for (int y = y0; y < yend; y++) {
        const float* rB = img + (size_t)min(y, HIN - 1) * WIN;
        float4 vB = *(const float4*)(rB + col);
        float lmB = __shfl_up_sync(0xffffffffu, vB.w, 1);
        if (lane == 0) lmB = (col > 0) ? rB[col - 1] : vB.x;

        const float la[4] = {lmA, vA.x, vA.y, vA.z};
        const float ra[4] = {vA.x, vA.y, vA.z, vA.w};
        const float lb[4] = {lmB, vB.x, vB.y, vB.z};
        const float rb[4] = {vB.x, vB.y, vB.z, vB.w};

        unsigned packed = 0;
        #pragma unroll
        for (int j = 0; j < 4; j++) {
            unsigned code = (lb[j] > 0.0f ? 1u : 0u) | (rb[j] > 0.0f ? 2u : 0u) |
                            (ra[j] > 0.0f ? 4u : 0u) | (la[j] > 0.0f ? 8u : 0u);
            packed |= code << (8 * j);
            c1 += (code - 1u) < 14u;
            c2 += (code == 5u) | (code == 10u);
        }
        unsigned char* crow = crow0 + (size_t)y * WCP;
        *(unsigned int*)(crow + col) = packed;
        if (t == TPB - 1) {                 // cell x = 1024 (clamped both sides)
            unsigned code = (vB.w > 0.0f ? 3u : 0u) | (vA.w > 0.0f ? 12u : 0u);
            crow[1024] = (unsigned char)code;
            c1 += (code - 1u) < 14u;
            c2 += (code == 5u) | (code == 10u);   // never true, kept for symmetry
        }
        vA = vB; lmA = lmB;                  // row reuse: bottom(y) == top(y+1)
    }

    // block reduction
    __shared__ unsigned r1[8], r2[8];
    const unsigned wid = t >> 5;
    unsigned s1 = __reduce_add_sync(0xffffffffu, c1);
    unsigned s2 = __reduce_add_sync(0xffffffffu, c2);
    if (lane == 0) { r1[wid] = s1; r2[wid] = s2; }
    __syncthreads();
    if (t == 0) {
        unsigned t1 = 0, t2 = 0;
        #pragma unroll
        for (int i = 0; i < 8; i++) { t1 += r1[i]; t2 += r2[i]; }
        g_cnt1[bk] = t1;
        g_cnt2[bk] = t2;
    }
}

// ------------- Scan: block offsets, group bases, counts, total -------------
__global__ void ms_scan(float* __restrict__ out, int out_size)
{
    __shared__ unsigned s1[NBLK], s2[NBLK];
    __shared__ unsigned t1[BATCH], t2[BATCH];
    __shared__ unsigned gb1[BATCH], gb2[BATCH];
    const int tid = threadIdx.x;
    for (int i = tid; i < NBLK; i += blockDim.x) { s1[i] = g_cnt1[i]; s2[i] = g_cnt2[i]; }
    __syncthreads();

    if (tid < BATCH) {
        unsigned s = 0;
        for (int i = 0; i < NBB; i++) s += s1[tid * NBB + i];
        t1[tid] = s;
    } else if (tid < 2 * BATCH) {
        const int b = tid - BATCH;
        unsigned s = 0;
        for (int i = 0; i < NBB; i++) s += s2[b * NBB + i];
        t2[b] = s;
    }
    __syncthreads();

    if (tid == 0) {
        unsigned acc = 0;
        for (int b = 0; b < BATCH; b++) {
            gb1[b] = acc; acc += t1[b];
            gb2[b] = acc; acc += t2[b];
        }
        g_total = acc;
    }
    __syncthreads();

    if (tid < BATCH && out_size >= NROWS * 4 + BATCH)
        out[(size_t)NROWS * 4 + tid] = (float)(t1[tid] + t2[tid]);

    if (tid < BATCH) {
        unsigned acc = gb1[tid];
        for (int i = 0; i < NBB; i++) {
            const unsigned v = s1[tid * NBB + i];
            g_off1[tid * NBB + i] = acc;
            acc += v;
        }
    } else if (tid < 2 * BATCH) {
        const int b = tid - BATCH;
        unsigned acc = gb2[b];
        for (int i = 0; i < NBB; i++) {
            const unsigned v = s2[b * NBB + i];
            g_off2[b * NBB + i] = acc;
            acc += v;
        }
    }
}

// ---------------- Pass 2: row-wise compaction + fused tail zero ------------
__global__ __launch_bounds__(TPB)
void ms_pass2(float4* __restrict__ out4)
{
    __shared__ unsigned ws[8];
    __shared__ unsigned sh_off1, sh_off2;

    const int bk    = blockIdx.x;
    const int b     = bk / NBB;
    const int chunk = bk - b * NBB;
    const int y0    = chunk * RPB;
    const int yend  = min(y0 + RPB, HC);
    const unsigned char* __restrict__ crow0 = g_codes + (size_t)b * CSTRIDE;

    const int t = threadIdx.x;
    const unsigned lane = t & 31u, wid = t >> 5;

    if (t == 0) { sh_off1 = g_off1[bk]; sh_off2 = g_off2[bk]; }

    for (int y = y0; y < yend; y++) {
        const unsigned char* crow = crow0 + (size_t)y * WCP;
        const unsigned packed = *(const unsigned int*)(crow + 4 * t);
        unsigned cd[4];
        cd[0] =  packed        & 255u;
        cd[1] = (packed >>  8) & 255u;
        cd[2] = (packed >> 16) & 255u;
        cd[3] =  packed >> 24;
        unsigned cX = 0;
        if (t == TPB - 1) cX = crow[1024];

        unsigned c1 = 0, c2 = 0;
        #pragma unroll
        for (int j = 0; j < 4; j++) {
            c1 += (cd[j] - 1u) < 14u;
            c2 += (cd[j] == 5u) | (cd[j] == 10u);
        }
        c1 += (cX - 1u) < 14u;
        c2 += (cX == 5u) | (cX == 10u);

        // block exclusive scan (16-bit packed: c1 | c2<<16)
        __syncthreads();                    // protect ws + sh_off ordering
        const unsigned v = c1 | (c2 << 16);
        unsigned inc = v;
        #pragma unroll
        for (int o = 1; o < 32; o <<= 1) {
            const unsigned u = __shfl_up_sync(0xffffffffu, inc, o);
            if (lane >= (unsigned)o) inc += u;
        }
        if (lane == 31) ws[wid] = inc;
        __syncthreads();
        if (t == 0) {
            unsigned acc = 0;
            #pragma unroll
            for (int i = 0; i < 8; i++) { const unsigned q = ws[i]; ws[i] = acc; acc += q; }
        }
        __syncthreads();
        const unsigned ex = inc - v + ws[wid];
        unsigned p1 = sh_off1 + (ex & 0xffffu);
        unsigned p2 = sh_off2 + (ex >> 16);
        __syncthreads();                    // all reads of sh_off done
        if (t == TPB - 1) {
            const unsigned tot = ex + v;    // row totals (inclusive of last thread)
            sh_off1 += tot & 0xffffu;
            sh_off2 += tot >> 16;
        }

        const float fy = (float)y;
        const float fx = (float)(4 * t);
        #pragma unroll
        for (int j = 0; j < 4; j++) {
            const unsigned code = cd[j];
            const float cx = fx + (float)j;
            if ((code - 1u) < 14u) {
                const float4 f = c_F[code];
                out4[p1++] = make_float4(fy + f.x, cx + f.y, fy + f.z, cx + f.w);
            }
            if (code == 5u)
                out4[p2++] = make_float4(fy, cx + 0.5f, fy - 0.5f, cx);
            else if (code == 10u)
                out4[p2++] = make_float4(fy - 0.5f, cx, fy, cx - 0.5f);
        }
        if (t == TPB - 1 && (cX - 1u) < 14u) {
            const float4 f = c_F[cX];
            const float cx = 1024.0f;
            out4[p1++] = make_float4(fy + f.x, cx + f.y, fy + f.z, cx + f.w);
        }
    }

    // fused tail zero: this block's slice of [g_total, NROWS)
    __syncthreads();
    const unsigned total = g_total;
    const unsigned tail  = (unsigned)NROWS - total;
    const unsigned cz    = (tail + NBLK - 1) / NBLK;
    const unsigned s     = total + (unsigned)bk * cz;
    const unsigned e     = min(s + cz, (unsigned)NROWS);
    const float4 z = make_float4(0.0f, 0.0f, 0.0f, 0.0f);
    for (unsigned i = s + t; i < e; i += TPB) out4[i] = z;
}

// ---------------------------------------------------------------------------
extern "C" void kernel_launch(void* const* d_in, const int* in_sizes, int n_in,
                              void* d_out, int out_size)
{
    const float* coarse = (const float*)d_in[0];
    float* out = (float*)d_out;

    ms_pass1<<<NBLK, TPB>>>(coarse);
    ms_scan<<<1, 1024>>>(out, out_size);
    ms_pass2<<<NBLK, TPB>>>((float4*)out);
}

// round 3
// speedup vs baseline: 2.3809x; 1.0115x over previous
#include <cuda_runtime.h>
#include <cuda_bf16.h>

// Problem geometry
#define BATCH   8
#define HIN     1024
#define WIN     1024
#define HC      1025               // code-grid rows
#define WC      1025               // code-grid cols
#define CELLS   (HC * WC)          // 1,050,625 cells per batch
#define WCP     1028               // padded code-row stride (mult of 4)
#define CSTRIDE (HC * WCP)         // per-batch code stride
#define RPB     8                  // cell-rows per block
#define NBB     129                // row-chunks per batch: ceil(1025/8)
#define NBLK    (BATCH * NBB)      // 1032 blocks
#define TPB     256
#define NROWS   (2 * BATCH * CELLS)  // 16,810,000 output rows (float4 each)

// -------- scratch (static device globals; no allocation allowed) ----------
__device__ unsigned char g_codes[(size_t)BATCH * CSTRIDE];
__device__ unsigned int  g_cnt1[NBLK];
__device__ unsigned int  g_cnt2[NBLK];
__device__ unsigned int  g_off1[NBLK];
__device__ unsigned int  g_off2[NBLK];
__device__ unsigned int  g_total;

// Midpoint offsets per code (FIRST table): row = [y+f.x, x+f.y, y+f.z, x+f.w]
__constant__ float4 c_F[16] = {
    { 0.0f,  0.0f,  0.0f,  0.0f},  // 0  (invalid)
    { 0.0f, -0.5f,  0.5f,  0.0f},  // 1
    { 0.5f,  0.0f,  0.0f,  0.5f},  // 2
    { 0.0f, -0.5f,  0.0f,  0.5f},  // 3
    { 0.0f,  0.5f, -0.5f,  0.0f},  // 4
    { 0.0f, -0.5f,  0.5f,  0.0f},  // 5
    { 0.5f,  0.0f, -0.5f,  0.0f},  // 6
    { 0.0f, -0.5f, -0.5f,  0.0f},  // 7
    {-0.5f,  0.0f,  0.0f, -0.5f},  // 8
    {-0.5f,  0.0f,  0.5f,  0.0f},  // 9
    { 0.5f,  0.0f,  0.0f,  0.5f},  // 10
    {-0.5f,  0.0f,  0.0f,  0.5f},  // 11
    { 0.0f,  0.5f,  0.0f, -0.5f},  // 12
    { 0.0f,  0.5f,  0.5f,  0.0f},  // 13
    { 0.5f,  0.0f,  0.0f, -0.5f},  // 14
    { 0.0f,  0.0f,  0.0f,  0.0f},  // 15 (invalid)
};
// SECOND[5] = (0, 0.5, -0.5, 0), SECOND[10] = (-0.5, 0, 0, -0.5) inlined.

// ---------------- Pass 1: codes + per-block counts (row-chunk blocks) ------
__global__ __launch_bounds__(TPB)
void ms_pass1(const float* __restrict__ in)
{
    const int bk    = blockIdx.x;
    const int b     = bk / NBB;
    const int chunk = bk - b * NBB;
    const int y0    = chunk * RPB;
    const int yend  = min(y0 + RPB, HC);
    const float* __restrict__ img = in + (size_t)b * HIN * WIN;
    unsigned char* __restrict__ crow0 = g_codes + (size_t)b * CSTRIDE;

    const int t    = threadIdx.x;
    const int col  = 4 * t;                  // 0..1020, float4 covers 4 cols
    const unsigned lane = t & 31u;

    // initial top row for y0: input row clamp(y0-1, 0, 1023)
    const float* rA = img + (size_t)max(min(y0 - 1, HIN - 1), 0) * WIN;
    float4 vA = *(const float4*)(rA + col);
    float lmA = __shfl_up_sync(0xffffffffu, vA.w, 1);
    if (lane == 0) lmA = (col > 0) ? rA[col - 1] : vA.x;

    unsigned c1 = 0, c2 = 0;

    for (int y = y0; y < yend; y++) {
        const float* rB = img + (size_t)min(y, HIN - 1) * WIN;
        float4 vB = *(const float4*)(rB + col);
        float lmB = __shfl_up_sync(0xffffffffu, vB.w, 1);
        if (lane == 0) lmB = (col > 0) ? rB[col - 1] : vB.x;

        const float la[4] = {lmA, vA.x, vA.y, vA.z};
        const float ra[4] = {vA.x, vA.y, vA.z, vA.w};
        const float lb[4] = {lmB, vB.x, vB.y, vB.z};
        const float rb[4] = {vB.x, vB.y, vB.z, vB.w};

        unsigned packed = 0;
        #pragma unroll
        for (int j = 0; j < 4; j++) {
            unsigned code = (lb[j] > 0.0f ? 1u : 0u) | (rb[j] > 0.0f ? 2u : 0u) |
                            (ra[j] > 0.0f ? 4u : 0u) | (la[j] > 0.0f ? 8u : 0u);
            packed |= code << (8 * j);
            c1 += (code - 1u) < 14u;
            c2 += (code == 5u) | (code == 10u);
        }
        unsigned char* crow = crow0 + (size_t)y * WCP;
        *(unsigned int*)(crow + col) = packed;
        if (t == TPB - 1) {                 // cell x = 1024 (clamped both sides)
            unsigned code = (vB.w > 0.0f ? 3u : 0u) | (vA.w > 0.0f ? 12u : 0u);
            crow[1024] = (unsigned char)code;
            c1 += (code - 1u) < 14u;
        }
        vA = vB; lmA = lmB;                  // row reuse: bottom(y) == top(y+1)
    }

    // block reduction
    __shared__ unsigned r1[8], r2[8];
    const unsigned wid = t >> 5;
    unsigned s1 = __reduce_add_sync(0xffffffffu, c1);
    unsigned s2 = __reduce_add_sync(0xffffffffu, c2);
    if (lane == 0) { r1[wid] = s1; r2[wid] = s2; }
    __syncthreads();
    if (t == 0) {
        unsigned t1 = 0, t2 = 0;
        #pragma unroll
        for (int i = 0; i < 8; i++) { t1 += r1[i]; t2 += r2[i]; }
        g_cnt1[bk] = t1;
        g_cnt2[bk] = t2;
    }
}

// ------------- Scan: block offsets, group bases, counts, total -------------
__global__ void ms_scan(float* __restrict__ out, int out_size)
{
    __shared__ unsigned s1[NBLK], s2[NBLK];
    __shared__ unsigned t1[BATCH], t2[BATCH];
    __shared__ unsigned gb1[BATCH], gb2[BATCH];
    const int tid = threadIdx.x;
    for (int i = tid; i < NBLK; i += blockDim.x) { s1[i] = g_cnt1[i]; s2[i] = g_cnt2[i]; }
    __syncthreads();

    if (tid < BATCH) {
        unsigned s = 0;
        for (int i = 0; i < NBB; i++) s += s1[tid * NBB + i];
        t1[tid] = s;
    } else if (tid < 2 * BATCH) {
        const int b = tid - BATCH;
        unsigned s = 0;
        for (int i = 0; i < NBB; i++) s += s2[b * NBB + i];
        t2[b] = s;
    }
    __syncthreads();

    if (tid == 0) {
        unsigned acc = 0;
        for (int b = 0; b < BATCH; b++) {
            gb1[b] = acc; acc += t1[b];
            gb2[b] = acc; acc += t2[b];
        }
        g_total = acc;
    }
    __syncthreads();

    if (tid < BATCH && out_size >= NROWS * 4 + BATCH)
        out[(size_t)NROWS * 4 + tid] = (float)(t1[tid] + t2[tid]);

    if (tid < BATCH) {
        unsigned acc = gb1[tid];
        for (int i = 0; i < NBB; i++) {
            const unsigned v = s1[tid * NBB + i];
            g_off1[tid * NBB + i] = acc;
            acc += v;
        }
    } else if (tid < 2 * BATCH) {
        const int b = tid - BATCH;
        unsigned acc = gb2[b];
        for (int i = 0; i < NBB; i++) {
            const unsigned v = s2[b * NBB + i];
            g_off2[b * NBB + i] = acc;
            acc += v;
        }
    }
}

// ------ Pass 2: smem-staged row compaction + coalesced flush + tail zero ---
__global__ __launch_bounds__(TPB)
void ms_pass2(float4* __restrict__ out4)
{
    __shared__ unsigned ws[8];
    __shared__ unsigned sh_n;                 // packed row totals (c1 | c2<<16)
    __shared__ float4 buf1[1026];
    __shared__ float4 buf2[1026];

    const int bk    = blockIdx.x;
    const int b     = bk / NBB;
    const int chunk = bk - b * NBB;
    const int y0    = chunk * RPB;
    const int yend  = min(y0 + RPB, HC);
    const unsigned char* __restrict__ crow0 = g_codes + (size_t)b * CSTRIDE;

    const int t = threadIdx.x;
    const unsigned lane = t & 31u, wid = t >> 5;

    unsigned off1 = g_off1[bk];               // uniform across block
    unsigned off2 = g_off2[bk];

    for (int y = y0; y < yend; y++) {
        const unsigned char* crow = crow0 + (size_t)y * WCP;
        const unsigned packed = *(const unsigned int*)(crow + 4 * t);
        unsigned cd[4];
        cd[0] =  packed        & 255u;
        cd[1] = (packed >>  8) & 255u;
        cd[2] = (packed >> 16) & 255u;
        cd[3] =  packed >> 24;
        unsigned cX = 0;
        if (t == TPB - 1) cX = crow[1024];

        unsigned c1 = 0, c2 = 0;
        #pragma unroll
        for (int j = 0; j < 4; j++) {
            c1 += (cd[j] - 1u) < 14u;
            c2 += (cd[j] == 5u) | (cd[j] == 10u);
        }
        c1 += (cX - 1u) < 14u;

        // block exclusive scan (16-bit packed: c1 | c2<<16)
        const unsigned v = c1 | (c2 << 16);
        unsigned inc = v;
        #pragma unroll
        for (int o = 1; o < 32; o <<= 1) {
            const unsigned u = __shfl_up_sync(0xffffffffu, inc, o);
            if (lane >= (unsigned)o) inc += u;
        }
        if (lane == 31) ws[wid] = inc;
        __syncthreads();
        if (t == 0) {
            unsigned acc = 0;
            #pragma unroll
            for (int i = 0; i < 8; i++) { const unsigned q = ws[i]; ws[i] = acc; acc += q; }
        }
        __syncthreads();
        const unsigned ex = inc - v + ws[wid];
        if (t == TPB - 1) sh_n = ex + v;      // block totals for this row
        unsigned p1 = ex & 0xffffu;
        unsigned p2 = ex >> 16;

        // stage compacted entries into shared memory
        const float fy = (float)y;
        const float fx = (float)(4 * t);
        #pragma unroll
        for (int j = 0; j < 4; j++) {
            const unsigned code = cd[j];
            const float cx = fx + (float)j;
            if ((code - 1u) < 14u) {
                const float4 f = c_F[code];
                buf1[p1++] = make_float4(fy + f.x, cx + f.y, fy + f.z, cx + f.w);
            }
            if (code == 5u)
                buf2[p2++] = make_float4(fy, cx + 0.5f, fy - 0.5f, cx);
            else if (code == 10u)
                buf2[p2++] = make_float4(fy - 0.5f, cx, fy, cx - 0.5f);
        }
        if (t == TPB - 1 && (cX - 1u) < 14u) {
            const float4 f = c_F[cX];
            buf1[p1++] = make_float4(fy + f.x, 1024.0f + f.y, fy + f.z, 1024.0f + f.w);
        }
        __syncthreads();

        // coalesced flush to gmem
        const unsigned n = sh_n;
        const unsigned n1 = n & 0xffffu;
        const unsigned n2 = n >> 16;
        for (unsigned i = t; i < n1; i += TPB) out4[off1 + i] = buf1[i];
        for (unsigned i = t; i < n2; i += TPB) out4[off2 + i] = buf2[i];
        off1 += n1;
        off2 += n2;
        __syncthreads();                      // buffers reused next row
    }

    // fused tail zero: this block's slice of [g_total, NROWS)
    const unsigned total = g_total;
    const unsigned tail  = (unsigned)NROWS - total;
    const unsigned cz    = (tail + NBLK - 1) / NBLK;
    const unsigned s     = total + (unsigned)bk * cz;
    const unsigned e     = min(s + cz, (unsigned)NROWS);
    const float4 z = make_float4(0.0f, 0.0f, 0.0f, 0.0f);
    for (unsigned i = s + t; i < e; i += TPB) out4[i] = z;
}

// ---------------------------------------------------------------------------
extern "C" void kernel_launch(void* const* d_in, const int* in_sizes, int n_in,
                              void* d_out, int out_size)
{
    const float* coarse = (const float*)d_in[0];
    float* out = (float*)d_out;

    ms_pass1<<<NBLK, TPB>>>(coarse);
    ms_scan<<<1, 1024>>>(out, out_size);
    ms_pass2<<<NBLK, TPB>>>((float4*)out);
}

// round 4
// speedup vs baseline: 2.6582x; 1.1165x over previous
#include <cuda_runtime.h>
#include <cuda_bf16.h>

// Problem geometry
#define BATCH   8
#define HIN     1024
#define WIN     1024
#define HC      1025               // code-grid rows
#define WC      1025               // code-grid cols
#define CELLS   (HC * WC)          // 1,050,625 cells per batch
#define WCP     1028               // padded code-row stride (mult of 4)
#define CSTRIDE (HC * WCP)         // per-batch code stride
#define RPB1    8                  // rows per pass1 block
#define NBB1    129                // pass1 chunks per batch: ceil(1025/8)
#define NBLK1   (BATCH * NBB1)     // 1032 pass1 blocks
#define RPB2    2                  // rows per pass2 block (wave balance)
#define NBB2    513                // pass2 chunks per batch: ceil(1025/2)
#define NBLK2   (BATCH * NBB2)     // 4104 pass2 blocks
#define TPB     256
#define NROWS   (2 * BATCH * CELLS)  // 16,810,000 output rows (float4 each)

// -------- scratch (static device globals; no allocation allowed) ----------
__device__ unsigned char g_codes[(size_t)BATCH * CSTRIDE];
__device__ unsigned int  g_cnt1[NBLK2];
__device__ unsigned int  g_cnt2[NBLK2];
__device__ unsigned int  g_off1[NBLK2];
__device__ unsigned int  g_off2[NBLK2];
__device__ unsigned int  g_total;

// Midpoint offsets per code (FIRST table): row = [y+f.x, x+f.y, y+f.z, x+f.w]
__constant__ float4 c_F[16] = {
    { 0.0f,  0.0f,  0.0f,  0.0f},  // 0  (invalid)
    { 0.0f, -0.5f,  0.5f,  0.0f},  // 1
    { 0.5f,  0.0f,  0.0f,  0.5f},  // 2
    { 0.0f, -0.5f,  0.0f,  0.5f},  // 3
    { 0.0f,  0.5f, -0.5f,  0.0f},  // 4
    { 0.0f, -0.5f,  0.5f,  0.0f},  // 5
    { 0.5f,  0.0f, -0.5f,  0.0f},  // 6
    { 0.0f, -0.5f, -0.5f,  0.0f},  // 7
    {-0.5f,  0.0f,  0.0f, -0.5f},  // 8
    {-0.5f,  0.0f,  0.5f,  0.0f},  // 9
    { 0.5f,  0.0f,  0.0f,  0.5f},  // 10
    {-0.5f,  0.0f,  0.0f,  0.5f},  // 11
    { 0.0f,  0.5f,  0.0f, -0.5f},  // 12
    { 0.0f,  0.5f,  0.5f,  0.0f},  // 13
    { 0.5f,  0.0f,  0.0f, -0.5f},  // 14
    { 0.0f,  0.0f,  0.0f,  0.0f},  // 15 (invalid)
};
// SECOND[5] = (0, 0.5, -0.5, 0), SECOND[10] = (-0.5, 0, 0, -0.5) inlined.

// ---------------- Pass 1: codes + per-2-row-subchunk counts ----------------
__global__ __launch_bounds__(TPB)
void ms_pass1(const float* __restrict__ in)
{
    const int bk    = blockIdx.x;
    const int b     = bk / NBB1;
    const int chunk = bk - b * NBB1;
    const int y0    = chunk * RPB1;
    const float* __restrict__ img = in + (size_t)b * HIN * WIN;
    unsigned char* __restrict__ crow0 = g_codes + (size_t)b * CSTRIDE;

    const int t    = threadIdx.x;
    const int col  = 4 * t;                  // 0..1020, float4 covers 4 cols
    const unsigned lane = t & 31u;
    const unsigned wid  = t >> 5;
    __shared__ unsigned r1[8], r2[8];

    // initial top row for y0: input row clamp(y0-1, 0, 1023)
    const float* rA = img + (size_t)max(min(y0 - 1, HIN - 1), 0) * WIN;
    float4 vA = *(const float4*)(rA + col);
    float lmA = __shfl_up_sync(0xffffffffu, vA.w, 1);
    if (lane == 0) lmA = (col > 0) ? rA[col - 1] : vA.x;

    #pragma unroll
    for (int sub = 0; sub < 4; sub++) {
        const int ys = y0 + 2 * sub;
        if (ys >= HC) break;                 // uniform across block
        const int ye = min(ys + 2, HC);
        unsigned c1 = 0, c2 = 0;

        for (int y = ys; y < ye; y++) {
            const float* rB = img + (size_t)min(y, HIN - 1) * WIN;
            float4 vB = *(const float4*)(rB + col);
            float lmB = __shfl_up_sync(0xffffffffu, vB.w, 1);
            if (lane == 0) lmB = (col > 0) ? rB[col - 1] : vB.x;

            const float la[4] = {lmA, vA.x, vA.y, vA.z};
            const float ra[4] = {vA.x, vA.y, vA.z, vA.w};
            const float lb[4] = {lmB, vB.x, vB.y, vB.z};
            const float rb[4] = {vB.x, vB.y, vB.z, vB.w};

            unsigned packed = 0;
            #pragma unroll
            for (int j = 0; j < 4; j++) {
                unsigned code = (lb[j] > 0.0f ? 1u : 0u) | (rb[j] > 0.0f ? 2u : 0u) |
                                (ra[j] > 0.0f ? 4u : 0u) | (la[j] > 0.0f ? 8u : 0u);
                packed |= code << (8 * j);
                c1 += (code - 1u) < 14u;
                c2 += (code == 5u) | (code == 10u);
            }
            unsigned char* crow = crow0 + (size_t)y * WCP;
            *(unsigned int*)(crow + col) = packed;
            if (t == TPB - 1) {              // cell x = 1024 (clamped both sides)
                unsigned code = (vB.w > 0.0f ? 3u : 0u) | (vA.w > 0.0f ? 12u : 0u);
                crow[1024] = (unsigned char)code;
                c1 += (code - 1u) < 14u;
            }
            vA = vB; lmA = lmB;              // row reuse: bottom(y) == top(y+1)
        }

        // block reduction for this 2-row subchunk
        unsigned s1 = __reduce_add_sync(0xffffffffu, c1);
        unsigned s2 = __reduce_add_sync(0xffffffffu, c2);
        __syncthreads();                     // r1/r2 reuse safety
        if (lane == 0) { r1[wid] = s1; r2[wid] = s2; }
        __syncthreads();
        if (t == 0) {
            unsigned t1 = 0, t2 = 0;
            #pragma unroll
            for (int i = 0; i < 8; i++) { t1 += r1[i]; t2 += r2[i]; }
            const int idx = b * NBB2 + chunk * 4 + sub;
            g_cnt1[idx] = t1;
            g_cnt2[idx] = t2;
        }
    }
}

// ------------- Scan: warp per (batch, table) group over NBB2 entries -------
__global__ __launch_bounds__(512)
void ms_scan(float* __restrict__ out, int out_size)
{
    __shared__ unsigned tot[16], gb[16];
    const int t = threadIdx.x;
    const int w = t >> 5;                    // group 0..15: (b<<1)|table
    const int lane = t & 31;
    const unsigned* __restrict__ cnt = (w & 1) ? g_cnt2 : g_cnt1;
    unsigned*       __restrict__ off = (w & 1) ? g_off2 : g_off1;
    const int base_i = (w >> 1) * NBB2;

    // group totals
    unsigned s = 0;
    for (int i = lane; i < NBB2; i += 32) s += cnt[base_i + i];
    s = __reduce_add_sync(0xffffffffu, s);
    if (lane == 0) tot[w] = s;
    __syncthreads();

    if (t == 0) {
        unsigned acc = 0;
        #pragma unroll
        for (int g = 0; g < 16; g++) { gb[g] = acc; acc += tot[g]; }
        g_total = acc;
    }
    __syncthreads();

    if (t < BATCH && out_size >= NROWS * 4 + BATCH)
        out[(size_t)NROWS * 4 + t] = (float)(tot[2 * t] + tot[2 * t + 1]);

    // exclusive scan within the group
    unsigned carry = gb[w];
    for (int i0 = 0; i0 < NBB2; i0 += 32) {
        const int i = i0 + lane;
        const unsigned v = (i < NBB2) ? cnt[base_i + i] : 0u;
        unsigned incl = v;
        #pragma unroll
        for (int o = 1; o < 32; o <<= 1) {
            const unsigned u = __shfl_up_sync(0xffffffffu, incl, o);
            if (lane >= o) incl += u;
        }
        if (i < NBB2) off[base_i + i] = carry + incl - v;
        carry += __shfl_sync(0xffffffffu, incl, 31);
    }
}

// ------ Pass 2: smem-staged row compaction + streaming flush + tail zero ---
__global__ __launch_bounds__(TPB)
void ms_pass2(float4* __restrict__ out4)
{
    __shared__ unsigned ws[8];
    __shared__ unsigned sh_n;                 // packed row totals (c1 | c2<<16)
    __shared__ float4 buf1[1026];
    __shared__ float4 buf2[1026];

    const int bk   = blockIdx.x;
    const int b    = bk / NBB2;
    const int ci   = bk - b * NBB2;
    const int y0   = ci * RPB2;
    const int yend = min(y0 + RPB2, HC);
    const unsigned char* __restrict__ crow0 = g_codes + (size_t)b * CSTRIDE;

    const int t = threadIdx.x;
    const unsigned lane = t & 31u, wid = t >> 5;

    unsigned off1 = g_off1[bk];               // uniform across block
    unsigned off2 = g_off2[bk];

    for (int y = y0; y < yend; y++) {
        const unsigned char* crow = crow0 + (size_t)y * WCP;
        const unsigned packed = *(const unsigned int*)(crow + 4 * t);
        unsigned cd[4];
        cd[0] =  packed        & 255u;
        cd[1] = (packed >>  8) & 255u;
        cd[2] = (packed >> 16) & 255u;
        cd[3] =  packed >> 24;
        unsigned cX = 0;
        if (t == TPB - 1) cX = crow[1024];

        unsigned c1 = 0, c2 = 0;
        #pragma unroll
        for (int j = 0; j < 4; j++) {
            c1 += (cd[j] - 1u) < 14u;
            c2 += (cd[j] == 5u) | (cd[j] == 10u);
        }
        c1 += (cX - 1u) < 14u;

        // block exclusive scan (16-bit packed: c1 | c2<<16)
        const unsigned v = c1 | (c2 << 16);
        unsigned inc = v;
        #pragma unroll
        for (int o = 1; o < 32; o <<= 1) {
            const unsigned u = __shfl_up_sync(0xffffffffu, inc, o);
            if (lane >= (unsigned)o) inc += u;
        }
        if (lane == 31) ws[wid] = inc;
        __syncthreads();
        if (t == 0) {
            unsigned acc = 0;
            #pragma unroll
            for (int i = 0; i < 8; i++) { const unsigned q = ws[i]; ws[i] = acc; acc += q; }
        }
        __syncthreads();
        const unsigned ex = inc - v + ws[wid];
        if (t == TPB - 1) sh_n = ex + v;      // block totals for this row
        unsigned p1 = ex & 0xffffu;
        unsigned p2 = ex >> 16;

        // stage compacted entries into shared memory
        const float fy = (float)y;
        const float fx = (float)(4 * t);
        #pragma unroll
        for (int j = 0; j < 4; j++) {
            const unsigned code = cd[j];
            const float cx = fx + (float)j;
            if ((code - 1u) < 14u) {
                const float4 f = c_F[code];
                buf1[p1++] = make_float4(fy + f.x, cx + f.y, fy + f.z, cx + f.w);
            }
            if (code == 5u)
                buf2[p2++] = make_float4(fy, cx + 0.5f, fy - 0.5f, cx);
            else if (code == 10u)
                buf2[p2++] = make_float4(fy - 0.5f, cx, fy, cx - 0.5f);
        }
        if (t == TPB - 1 && (cX - 1u) < 14u) {
            const float4 f = c_F[cX];
            buf1[p1++] = make_float4(fy + f.x, 1024.0f + f.y, fy + f.z, 1024.0f + f.w);
        }
        __syncthreads();

        // streaming (evict-first) coalesced flush to gmem
        const unsigned n = sh_n;
        const unsigned n1 = n & 0xffffu;
        const unsigned n2 = n >> 16;
        for (unsigned i = t; i < n1; i += TPB) __stcs(&out4[off1 + i], buf1[i]);
        for (unsigned i = t; i < n2; i += TPB) __stcs(&out4[off2 + i], buf2[i]);
        off1 += n1;
        off2 += n2;
        __syncthreads();                      // buffers reused next row
    }

    // fused tail zero: this block's slice of [g_total, NROWS)
    const unsigned total = g_total;
    const unsigned tail  = (unsigned)NROWS - total;
    const unsigned cz    = (tail + NBLK2 - 1) / NBLK2;
    const unsigned s     = total + (unsigned)bk * cz;
    const unsigned e     = min(s + cz, (unsigned)NROWS);
    const float4 z = make_float4(0.0f, 0.0f, 0.0f, 0.0f);
    for (unsigned i = s + t; i < e; i += TPB) __stcs(&out4[i], z);
}

// ---------------------------------------------------------------------------
extern "C" void kernel_launch(void* const* d_in, const int* in_sizes, int n_in,
                              void* d_out, int out_size)
{
    const float* coarse = (const float*)d_in[0];
    float* out = (float*)d_out;

    ms_pass1<<<NBLK1, TPB>>>(coarse);
    ms_scan<<<1, 512>>>(out, out_size);
    ms_pass2<<<NBLK2, TPB>>>((float4*)out);
}

// round 5
// speedup vs baseline: 2.6685x; 1.0039x over previous
#include <cuda_runtime.h>
#include <cuda_bf16.h>

// Problem geometry
#define BATCH   8
#define HIN     1024
#define WIN     1024
#define HC      1025               // code-grid rows
#define WC      1025               // code-grid cols
#define CELLS   (HC * WC)          // 1,050,625 cells per batch
#define WCP     1028               // padded code-row stride (mult of 4)
#define CSTRIDE (HC * WCP)         // per-batch code stride
#define RPB1    8                  // rows per pass1 block
#define NBB1    129                // pass1 chunks per batch: ceil(1025/8)
#define NBLK1   (BATCH * NBB1)     // 1032 pass1 blocks
#define RPB2    2                  // rows per pass2 block (wave balance)
#define NBB2    513                // pass2 chunks per batch: ceil(1025/2)
#define NBLK2   (BATCH * NBB2)     // 4104 pass2 blocks
#define TPB     256
#define NROWS   (2 * BATCH * CELLS)  // 16,810,000 output rows (float4 each)

// -------- scratch (static device globals; no allocation allowed) ----------
__device__ unsigned char g_codes[(size_t)BATCH * CSTRIDE];
__device__ unsigned int  g_cnt1[NBLK2];
__device__ unsigned int  g_cnt2[NBLK2];
__device__ unsigned int  g_off1[NBLK2];
__device__ unsigned int  g_off2[NBLK2];
__device__ unsigned int  g_total;

// Midpoint offsets per code (FIRST table): row = [y+f.x, x+f.y, y+f.z, x+f.w]
__constant__ float4 c_F[16] = {
    { 0.0f,  0.0f,  0.0f,  0.0f},  // 0  (invalid)
    { 0.0f, -0.5f,  0.5f,  0.0f},  // 1
    { 0.5f,  0.0f,  0.0f,  0.5f},  // 2
    { 0.0f, -0.5f,  0.0f,  0.5f},  // 3
    { 0.0f,  0.5f, -0.5f,  0.0f},  // 4
    { 0.0f, -0.5f,  0.5f,  0.0f},  // 5
    { 0.5f,  0.0f, -0.5f,  0.0f},  // 6
    { 0.0f, -0.5f, -0.5f,  0.0f},  // 7
    {-0.5f,  0.0f,  0.0f, -0.5f},  // 8
    {-0.5f,  0.0f,  0.5f,  0.0f},  // 9
    { 0.5f,  0.0f,  0.0f,  0.5f},  // 10
    {-0.5f,  0.0f,  0.0f,  0.5f},  // 11
    { 0.0f,  0.5f,  0.0f, -0.5f},  // 12
    { 0.0f,  0.5f,  0.5f,  0.0f},  // 13
    { 0.5f,  0.0f,  0.0f, -0.5f},  // 14
    { 0.0f,  0.0f,  0.0f,  0.0f},  // 15 (invalid)
};
// SECOND[5] = (0, 0.5, -0.5, 0), SECOND[10] = (-0.5, 0, 0, -0.5) inlined.

// ---------------- Pass 1: codes + per-2-row-subchunk counts ----------------
__global__ __launch_bounds__(TPB)
void ms_pass1(const float* __restrict__ in)
{
    const int bk    = blockIdx.x;
    const int b     = bk / NBB1;
    const int chunk = bk - b * NBB1;
    const int y0    = chunk * RPB1;
    const float* __restrict__ img = in + (size_t)b * HIN * WIN;
    unsigned char* __restrict__ crow0 = g_codes + (size_t)b * CSTRIDE;

    const int t    = threadIdx.x;
    const int col  = 4 * t;                  // 0..1020, float4 covers 4 cols
    const unsigned lane = t & 31u;
    const unsigned wid  = t >> 5;
    __shared__ unsigned r1[8], r2[8];

    // initial top row for y0: input row clamp(y0-1, 0, 1023)
    const float* rA = img + (size_t)max(min(y0 - 1, HIN - 1), 0) * WIN;
    float4 vA = *(const float4*)(rA + col);
    float lmA = __shfl_up_sync(0xffffffffu, vA.w, 1);
    if (lane == 0) lmA = (col > 0) ? rA[col - 1] : vA.x;

    #pragma unroll
    for (int sub = 0; sub < 4; sub++) {
        const int ys = y0 + 2 * sub;
        if (ys >= HC) break;                 // uniform across block
        const int ye = min(ys + 2, HC);
        unsigned c1 = 0, c2 = 0;

        for (int y = ys; y < ye; y++) {
            const float* rB = img + (size_t)min(y, HIN - 1) * WIN;
            float4 vB = *(const float4*)(rB + col);
            float lmB = __shfl_up_sync(0xffffffffu, vB.w, 1);
            if (lane == 0) lmB = (col > 0) ? rB[col - 1] : vB.x;

            const float la[4] = {lmA, vA.x, vA.y, vA.z};
            const float ra[4] = {vA.x, vA.y, vA.z, vA.w};
            const float lb[4] = {lmB, vB.x, vB.y, vB.z};
            const float rb[4] = {vB.x, vB.y, vB.z, vB.w};

            unsigned packed = 0;
            #pragma unroll
            for (int j = 0; j < 4; j++) {
                unsigned code = (lb[j] > 0.0f ? 1u : 0u) | (rb[j] > 0.0f ? 2u : 0u) |
                                (ra[j] > 0.0f ? 4u : 0u) | (la[j] > 0.0f ? 8u : 0u);
                packed |= code << (8 * j);
                c1 += (code - 1u) < 14u;
                c2 += (code == 5u) | (code == 10u);
            }
            unsigned char* crow = crow0 + (size_t)y * WCP;
            *(unsigned int*)(crow + col) = packed;
            if (t == TPB - 1) {              // cell x = 1024 (clamped both sides)
                unsigned code = (vB.w > 0.0f ? 3u : 0u) | (vA.w > 0.0f ? 12u : 0u);
                crow[1024] = (unsigned char)code;
                c1 += (code - 1u) < 14u;
            }
            vA = vB; lmA = lmB;              // row reuse: bottom(y) == top(y+1)
        }

        // block reduction for this 2-row subchunk
        unsigned s1 = __reduce_add_sync(0xffffffffu, c1);
        unsigned s2 = __reduce_add_sync(0xffffffffu, c2);
        __syncthreads();                     // r1/r2 reuse safety
        if (lane == 0) { r1[wid] = s1; r2[wid] = s2; }
        __syncthreads();
        if (t == 0) {
            unsigned t1 = 0, t2 = 0;
            #pragma unroll
            for (int i = 0; i < 8; i++) { t1 += r1[i]; t2 += r2[i]; }
            const int idx = b * NBB2 + chunk * 4 + sub;
            g_cnt1[idx] = t1;
            g_cnt2[idx] = t2;
        }
    }
}

// ------------- Scan: warp per (batch, table) group over NBB2 entries -------
__global__ __launch_bounds__(512)
void ms_scan(float* __restrict__ out, int out_size)
{
    __shared__ unsigned tot[16], gb[16];
    const int t = threadIdx.x;
    const int w = t >> 5;                    // group 0..15: (b<<1)|table
    const int lane = t & 31;
    const unsigned* __restrict__ cnt = (w & 1) ? g_cnt2 : g_cnt1;
    unsigned*       __restrict__ off = (w & 1) ? g_off2 : g_off1;
    const int base_i = (w >> 1) * NBB2;

    // group totals
    unsigned s = 0;
    for (int i = lane; i < NBB2; i += 32) s += cnt[base_i + i];
    s = __reduce_add_sync(0xffffffffu, s);
    if (lane == 0) tot[w] = s;
    __syncthreads();

    if (t == 0) {
        unsigned acc = 0;
        #pragma unroll
        for (int g = 0; g < 16; g++) { gb[g] = acc; acc += tot[g]; }
        g_total = acc;
    }
    __syncthreads();

    if (t < BATCH && out_size >= NROWS * 4 + BATCH)
        out[(size_t)NROWS * 4 + t] = (float)(tot[2 * t] + tot[2 * t + 1]);

    // exclusive scan within the group
    unsigned carry = gb[w];
    for (int i0 = 0; i0 < NBB2; i0 += 32) {
        const int i = i0 + lane;
        const unsigned v = (i < NBB2) ? cnt[base_i + i] : 0u;
        unsigned incl = v;
        #pragma unroll
        for (int o = 1; o < 32; o <<= 1) {
            const unsigned u = __shfl_up_sync(0xffffffffu, incl, o);
            if (lane >= o) incl += u;
        }
        if (i < NBB2) off[base_i + i] = carry + incl - v;
        carry += __shfl_sync(0xffffffffu, incl, 31);
    }
}

// ------ Pass 2: smem-staged row compaction + coalesced flush + tail zero ---
__global__ __launch_bounds__(TPB)
void ms_pass2(float4* __restrict__ out4)
{
    __shared__ unsigned ws[8];
    __shared__ unsigned sh_n;                 // packed row totals (c1 | c2<<16)
    __shared__ float4 buf1[1026];
    __shared__ float4 buf2[1026];

    const int bk   = blockIdx.x;
    const int b    = bk / NBB2;
    const int ci   = bk - b * NBB2;
    const int y0   = ci * RPB2;
    const int yend = min(y0 + RPB2, HC);
    const unsigned char* __restrict__ crow0 = g_codes + (size_t)b * CSTRIDE;

    const int t = threadIdx.x;
    const unsigned lane = t & 31u, wid = t >> 5;

    unsigned off1 = g_off1[bk];               // uniform across block
    unsigned off2 = g_off2[bk];

    for (int y = y0; y < yend; y++) {
        const unsigned char* crow = crow0 + (size_t)y * WCP;
        const unsigned packed = *(const unsigned int*)(crow + 4 * t);
        unsigned cd[4];
        cd[0] =  packed        & 255u;
        cd[1] = (packed >>  8) & 255u;
        cd[2] = (packed >> 16) & 255u;
        cd[3] =  packed >> 24;
        unsigned cX = 0;
        if (t == TPB - 1) cX = crow[1024];

        unsigned c1 = 0, c2 = 0;
        #pragma unroll
        for (int j = 0; j < 4; j++) {
            c1 += (cd[j] - 1u) < 14u;
            c2 += (cd[j] == 5u) | (cd[j] == 10u);
        }
        c1 += (cX - 1u) < 14u;

        // block exclusive scan (16-bit packed: c1 | c2<<16)
        const unsigned v = c1 | (c2 << 16);
        unsigned inc = v;
        #pragma unroll
        for (int o = 1; o < 32; o <<= 1) {
            const unsigned u = __shfl_up_sync(0xffffffffu, inc, o);
            if (lane >= (unsigned)o) inc += u;
        }
        if (lane == 31) ws[wid] = inc;
        __syncthreads();
        if (t == 0) {
            unsigned acc = 0;
            #pragma unroll
            for (int i = 0; i < 8; i++) { const unsigned q = ws[i]; ws[i] = acc; acc += q; }
        }
        __syncthreads();
        const unsigned ex = inc - v + ws[wid];
        if (t == TPB - 1) sh_n = ex + v;      // block totals for this row
        unsigned p1 = ex & 0xffffu;
        unsigned p2 = ex >> 16;

        // stage compacted entries into shared memory
        const float fy = (float)y;
        const float fx = (float)(4 * t);
        #pragma unroll
        for (int j = 0; j < 4; j++) {
            const unsigned code = cd[j];
            const float cx = fx + (float)j;
            if ((code - 1u) < 14u) {
                const float4 f = c_F[code];
                buf1[p1++] = make_float4(fy + f.x, cx + f.y, fy + f.z, cx + f.w);
            }
            if (code == 5u)
                buf2[p2++] = make_float4(fy, cx + 0.5f, fy - 0.5f, cx);
            else if (code == 10u)
                buf2[p2++] = make_float4(fy - 0.5f, cx, fy, cx - 0.5f);
        }
        if (t == TPB - 1 && (cX - 1u) < 14u) {
            const float4 f = c_F[cX];
            buf1[p1++] = make_float4(fy + f.x, 1024.0f + f.y, fy + f.z, 1024.0f + f.w);
        }
        __syncthreads();

        // coalesced flush to gmem — DEFAULT caching (let L2 merge half-sectors
        // into full lines before eviction; __stcs here halves write BW)
        const unsigned n = sh_n;
        const unsigned n1 = n & 0xffffu;
        const unsigned n2 = n >> 16;
        for (unsigned i = t; i < n1; i += TPB) out4[off1 + i] = buf1[i];
        for (unsigned i = t; i < n2; i += TPB) out4[off2 + i] = buf2[i];
        off1 += n1;
        off2 += n2;
        __syncthreads();                      // buffers reused next row
    }

    // fused tail zero: this block's slice of [g_total, NROWS)
    // (fully coalesced full-line writes -> streaming hint is safe + saves L2)
    const unsigned total = g_total;
    const unsigned tail  = (unsigned)NROWS - total;
    const unsigned cz    = (tail + NBLK2 - 1) / NBLK2;
    const unsigned s     = total + (unsigned)bk * cz;
    const unsigned e     = min(s + cz, (unsigned)NROWS);
    const float4 z = make_float4(0.0f, 0.0f, 0.0f, 0.0f);
    for (unsigned i = s + t; i < e; i += TPB) __stcs(&out4[i], z);
}

// ---------------------------------------------------------------------------
extern "C" void kernel_launch(void* const* d_in, const int* in_sizes, int n_in,
                              void* d_out, int out_size)
{
    const float* coarse = (const float*)d_in[0];
    float* out = (float*)d_out;

    ms_pass1<<<NBLK1, TPB>>>(coarse);
    ms_scan<<<1, 512>>>(out, out_size);
    ms_pass2<<<NBLK2, TPB>>>((float4*)out);
}

// round 6
// speedup vs baseline: 2.7537x; 1.0319x over previous
#include <cuda_runtime.h>
#include <cuda_bf16.h>

// Problem geometry
#define BATCH   8
#define HIN     1024
#define WIN     1024
#define HC      1025               // code-grid rows
#define WC      1025               // code-grid cols
#define CELLS   (HC * WC)          // 1,050,625 cells per batch
#define WCP     1028               // padded code-row stride (mult of 4)
#define CSTRIDE (HC * WCP)         // per-batch code stride
#define RPB1    8                  // rows per pass1 block
#define NBB1    129                // pass1 chunks per batch: ceil(1025/8)
#define NBLK1   (BATCH * NBB1)     // 1032 pass1 blocks
#define RPB2    2                  // rows per pass2 block (wave balance)
#define NBB2    513                // pass2 chunks per batch: ceil(1025/2)
#define NBLK2   (BATCH * NBB2)     // 4104 pass2 blocks
#define TPB     256
#define NROWS   (2 * BATCH * CELLS)  // 16,810,000 output rows (float4 each)

// -------- scratch (static device globals; no allocation allowed) ----------
__device__ unsigned char g_codes[(size_t)BATCH * CSTRIDE];
__device__ unsigned int  g_cnt1[NBLK2];
__device__ unsigned int  g_cnt2[NBLK2];
__device__ unsigned int  g_off1[NBLK2];
__device__ unsigned int  g_off2[NBLK2];
__device__ unsigned int  g_total;
__device__ unsigned int  g_done;     // zero-init; reset by last block each launch

// Midpoint offsets per code (FIRST table): row = [y+f.x, x+f.y, y+f.z, x+f.w]
__constant__ float4 c_F[16] = {
    { 0.0f,  0.0f,  0.0f,  0.0f},  // 0  (invalid)
    { 0.0f, -0.5f,  0.5f,  0.0f},  // 1
    { 0.5f,  0.0f,  0.0f,  0.5f},  // 2
    { 0.0f, -0.5f,  0.0f,  0.5f},  // 3
    { 0.0f,  0.5f, -0.5f,  0.0f},  // 4
    { 0.0f, -0.5f,  0.5f,  0.0f},  // 5
    { 0.5f,  0.0f, -0.5f,  0.0f},  // 6
    { 0.0f, -0.5f, -0.5f,  0.0f},  // 7
    {-0.5f,  0.0f,  0.0f, -0.5f},  // 8
    {-0.5f,  0.0f,  0.5f,  0.0f},  // 9
    { 0.5f,  0.0f,  0.0f,  0.5f},  // 10
    {-0.5f,  0.0f,  0.0f,  0.5f},  // 11
    { 0.0f,  0.5f,  0.0f, -0.5f},  // 12
    { 0.0f,  0.5f,  0.5f,  0.0f},  // 13
    { 0.5f,  0.0f,  0.0f, -0.5f},  // 14
    { 0.0f,  0.0f,  0.0f,  0.0f},  // 15 (invalid)
};
// SECOND[5] = (0, 0.5, -0.5, 0), SECOND[10] = (-0.5, 0, 0, -0.5) inlined.

// ------- Pass 1: codes + per-2-row-subchunk counts + inline final scan -----
__global__ __launch_bounds__(TPB, 8)
void ms_pass1(const float* __restrict__ in, float* __restrict__ out, int out_size)
{
    const int bk    = blockIdx.x;
    const int b     = bk / NBB1;
    const int chunk = bk - b * NBB1;
    const int y0    = chunk * RPB1;
    const float* __restrict__ img = in + (size_t)b * HIN * WIN;
    unsigned char* __restrict__ crow0 = g_codes + (size_t)b * CSTRIDE;

    const int t    = threadIdx.x;
    const int col  = 4 * t;                  // 0..1020, float4 covers 4 cols
    const int lane = t & 31;
    const int wid  = t >> 5;
    __shared__ unsigned r1[8], r2[8];

    // initial top row for y0: input row clamp(y0-1, 0, 1023)
    const float* rA = img + (size_t)max(min(y0 - 1, HIN - 1), 0) * WIN;
    float4 vA = *(const float4*)(rA + col);
    float lmA = __shfl_up_sync(0xffffffffu, vA.w, 1);
    if (lane == 0) lmA = (col > 0) ? rA[col - 1] : vA.x;

    #pragma unroll
    for (int sub = 0; sub < 4; sub++) {
        const int ys = y0 + 2 * sub;
        if (ys >= HC) break;                 // uniform across block
        const int ye = min(ys + 2, HC);
        unsigned c1 = 0, c2 = 0;

        for (int y = ys; y < ye; y++) {
            const float* rB = img + (size_t)min(y, HIN - 1) * WIN;
            float4 vB = *(const float4*)(rB + col);
            float lmB = __shfl_up_sync(0xffffffffu, vB.w, 1);
            if (lane == 0) lmB = (col > 0) ? rB[col - 1] : vB.x;

            const float la[4] = {lmA, vA.x, vA.y, vA.z};
            const float ra[4] = {vA.x, vA.y, vA.z, vA.w};
            const float lb[4] = {lmB, vB.x, vB.y, vB.z};
            const float rb[4] = {vB.x, vB.y, vB.z, vB.w};

            unsigned packed = 0;
            #pragma unroll
            for (int j = 0; j < 4; j++) {
                unsigned code = (lb[j] > 0.0f ? 1u : 0u) | (rb[j] > 0.0f ? 2u : 0u) |
                                (ra[j] > 0.0f ? 4u : 0u) | (la[j] > 0.0f ? 8u : 0u);
                packed |= code << (8 * j);
                c1 += (code - 1u) < 14u;
                c2 += (code == 5u) | (code == 10u);
            }
            unsigned char* crow = crow0 + (size_t)y * WCP;
            *(unsigned int*)(crow + col) = packed;
            if (t == TPB - 1) {              // cell x = 1024 (clamped both sides)
                unsigned code = (vB.w > 0.0f ? 3u : 0u) | (vA.w > 0.0f ? 12u : 0u);
                crow[1024] = (unsigned char)code;
                c1 += (code - 1u) < 14u;
            }
            vA = vB; lmA = lmB;              // row reuse: bottom(y) == top(y+1)
        }

        // block reduction for this 2-row subchunk
        unsigned s1 = __reduce_add_sync(0xffffffffu, c1);
        unsigned s2 = __reduce_add_sync(0xffffffffu, c2);
        __syncthreads();                     // r1/r2 reuse safety
        if (lane == 0) { r1[wid] = s1; r2[wid] = s2; }
        __syncthreads();
        if (t == 0) {
            unsigned t1 = 0, t2 = 0;
            #pragma unroll
            for (int i = 0; i < 8; i++) { t1 += r1[i]; t2 += r2[i]; }
            const int idx = b * NBB2 + chunk * 4 + sub;
            g_cnt1[idx] = t1;
            g_cnt2[idx] = t2;
        }
    }

    // ---- last-block-done: final block performs the global scan inline -----
    __shared__ unsigned slast;
    if (t == 0) {
        __threadfence();                     // publish g_cnt before counter
        const bool last = (atomicAdd(&g_done, 1u) == (unsigned)(NBLK1 - 1));
        if (last) g_done = 0;                // reset for next launch
        slast = last ? 1u : 0u;
    }
    __syncthreads();
    if (!slast) return;
    __threadfence();                         // acquire: see all g_cnt writes

    __shared__ unsigned tot[16], gbs[17];
    // Phase A: totals per group (warp wid handles groups 2*wid, 2*wid+1)
    #pragma unroll
    for (int rep = 0; rep < 2; rep++) {
        const int g = wid * 2 + rep;
        const unsigned* __restrict__ cnt = (g & 1) ? g_cnt2 : g_cnt1;
        const int base = (g >> 1) * NBB2;
        const int i0 = lane * 17;
        unsigned s = 0;
        #pragma unroll
        for (int j = 0; j < 17; j++) {
            const int i = i0 + j;
            if (i < NBB2) s += cnt[base + i];
        }
        s = __reduce_add_sync(0xffffffffu, s);
        if (lane == 0) tot[g] = s;
    }
    __syncthreads();
    if (t == 0) {
        unsigned acc = 0;
        #pragma unroll
        for (int g = 0; g < 16; g++) { gbs[g] = acc; acc += tot[g]; }
        gbs[16] = acc;
        g_total = acc;
    }
    __syncthreads();
    if (t < BATCH && out_size >= NROWS * 4 + BATCH)
        out[(size_t)NROWS * 4 + t] = (float)(tot[2 * t] + tot[2 * t + 1]);

    // Phase C: exclusive offsets (register-resident, 17 entries per lane)
    #pragma unroll
    for (int rep = 0; rep < 2; rep++) {
        const int g = wid * 2 + rep;
        const unsigned* __restrict__ cnt = (g & 1) ? g_cnt2 : g_cnt1;
        unsigned*       __restrict__ off = (g & 1) ? g_off2 : g_off1;
        const int base = (g >> 1) * NBB2;
        const int i0 = lane * 17;
        unsigned v[17];
        unsigned s = 0;
        #pragma unroll
        for (int j = 0; j < 17; j++) {
            const int i = i0 + j;
            v[j] = (i < NBB2) ? cnt[base + i] : 0u;
            s += v[j];
        }
        unsigned incl = s;
        #pragma unroll
        for (int o = 1; o < 32; o <<= 1) {
            const unsigned u = __shfl_up_sync(0xffffffffu, incl, o);
            if (lane >= o) incl += u;
        }
        unsigned run = gbs[g] + incl - s;    // exclusive base for this lane
        #pragma unroll
        for (int j = 0; j < 17; j++) {
            const int i = i0 + j;
            if (i < NBB2) off[base + i] = run;
            run += v[j];
        }
    }
}

// ------ Pass 2: smem-staged row compaction + WT flush + fused tail zero ----
__global__ __launch_bounds__(TPB)
void ms_pass2(float4* __restrict__ out4)
{
    __shared__ unsigned ws[8];
    __shared__ unsigned sh_n;                 // packed row totals (c1 | c2<<16)
    __shared__ float4 buf1[1026];
    __shared__ float4 buf2[1026];

    const int bk   = blockIdx.x;
    const int b    = bk / NBB2;
    const int ci   = bk - b * NBB2;
    const int y0   = ci * RPB2;
    const int nrows = min(y0 + RPB2, HC) - y0;
    const unsigned char* __restrict__ crow0 = g_codes + (size_t)b * CSTRIDE;

    const int t = threadIdx.x;
    const unsigned lane = t & 31u, wid = t >> 5;

    unsigned off1 = g_off1[bk];               // uniform across block
    unsigned off2 = g_off2[bk];

    // prefetch both rows' code words (MLP across the two row phases)
    unsigned packs[2], cXs[2];
    #pragma unroll
    for (int r = 0; r < 2; r++) {
        if (r < nrows) {
            const unsigned char* crow = crow0 + (size_t)(y0 + r) * WCP;
            packs[r] = *(const unsigned int*)(crow + 4 * t);
            cXs[r]   = (t == TPB - 1) ? (unsigned)crow[1024] : 0u;
        } else { packs[r] = 0u; cXs[r] = 0u; }
    }

    #pragma unroll
    for (int r = 0; r < 2; r++) {
        if (r >= nrows) break;
        const int y = y0 + r;
        const unsigned packed = packs[r];
        unsigned cd[4];
        cd[0] =  packed        & 255u;
        cd[1] = (packed >>  8) & 255u;
        cd[2] = (packed >> 16) & 255u;
        cd[3] =  packed >> 24;
        const unsigned cX = cXs[r];

        unsigned c1 = 0, c2 = 0;
        #pragma unroll
        for (int j = 0; j < 4; j++) {
            c1 += (cd[j] - 1u) < 14u;
            c2 += (cd[j] == 5u) | (cd[j] == 10u);
        }
        c1 += (cX - 1u) < 14u;

        // block exclusive scan (16-bit packed: c1 | c2<<16)
        const unsigned v = c1 | (c2 << 16);
        unsigned inc = v;
        #pragma unroll
        for (int o = 1; o < 32; o <<= 1) {
            const unsigned u = __shfl_up_sync(0xffffffffu, inc, o);
            if (lane >= (unsigned)o) inc += u;
        }
        if (lane == 31) ws[wid] = inc;
        __syncthreads();
        if (t == 0) {
            unsigned acc = 0;
            #pragma unroll
            for (int i = 0; i < 8; i++) { const unsigned q = ws[i]; ws[i] = acc; acc += q; }
        }
        __syncthreads();
        const unsigned ex = inc - v + ws[wid];
        if (t == TPB - 1) sh_n = ex + v;      // block totals for this row
        unsigned p1 = ex & 0xffffu;
        unsigned p2 = ex >> 16;

        // stage compacted entries into shared memory
        const float fy = (float)y;
        const float fx = (float)(4 * t);
        #pragma unroll
        for (int j = 0; j < 4; j++) {
            const unsigned code = cd[j];
            const float cx = fx + (float)j;
            if ((code - 1u) < 14u) {
                const float4 f = c_F[code];
                buf1[p1++] = make_float4(fy + f.x, cx + f.y, fy + f.z, cx + f.w);
            }
            if (code == 5u)
                buf2[p2++] = make_float4(fy, cx + 0.5f, fy - 0.5f, cx);
            else if (code == 10u)
                buf2[p2++] = make_float4(fy - 0.5f, cx, fy, cx - 0.5f);
        }
        if (t == TPB - 1 && (cX - 1u) < 14u) {
            const float4 f = c_F[cX];
            buf1[p1++] = make_float4(fy + f.x, 1024.0f + f.y, fy + f.z, 1024.0f + f.w);
        }
        __syncthreads();

        // coalesced flush to gmem — write-through (no L2 allocate: output is
        // write-once, never re-read; avoid L2 writeback machinery entirely)
        const unsigned n = sh_n;
        const unsigned n1 = n & 0xffffu;
        const unsigned n2 = n >> 16;
        for (unsigned i = t; i < n1; i += TPB) __stwt(&out4[off1 + i], buf1[i]);
        for (unsigned i = t; i < n2; i += TPB) __stwt(&out4[off2 + i], buf2[i]);
        off1 += n1;
        off2 += n2;
        __syncthreads();                      // buffers reused next row
    }

    // fused tail zero: this block's slice of [g_total, NROWS)
    const unsigned total = g_total;
    const unsigned tail  = (unsigned)NROWS - total;
    const unsigned cz    = (tail + NBLK2 - 1) / NBLK2;
    const unsigned s     = total + (unsigned)bk * cz;
    const unsigned e     = min(s + cz, (unsigned)NROWS);
    const float4 z = make_float4(0.0f, 0.0f, 0.0f, 0.0f);
    for (unsigned i = s + t; i < e; i += TPB) __stwt(&out4[i], z);
}

// ---------------------------------------------------------------------------
extern "C" void kernel_launch(void* const* d_in, const int* in_sizes, int n_in,
                              void* d_out, int out_size)
{
    const float* coarse = (const float*)d_in[0];
    float* out = (float*)d_out;

    ms_pass1<<<NBLK1, TPB>>>(coarse, out, out_size);
    ms_pass2<<<NBLK2, TPB>>>((float4*)out);
}